// round 1
// baseline (speedup 1.0000x reference)
#include <cuda_runtime.h>
#include <math.h>

// Problem dims
#define Sd 32
#define Wd 64
#define Dd 256
#define Hd 256
#define Td (Sd*Wd)      // 2048
#define R4H 1024        // 4*H
#define Gn 16           // CTAs in recurrence
#define HSL (Hd/Gn)     // 16 hidden units per CTA
#define RECTHREADS 512

// ---------------- device scratch (static, no allocation) ----------------
__device__ float g_Xp1[Td*R4H];        // 8 MB: W_ih1@x + b1 for all word steps
__device__ float g_Xp2[Sd*R4H];        // W_ih2@sentVec + b2
__device__ float g_Hwords[Td*Hd];      // all word-LSTM hiddens
__device__ float g_rowH[Sd*Hd];        // all sentence-LSTM hiddens
__device__ float g_sc1[Td];            // word attention exp-scores
__device__ float g_sc2[Sd];            // sentence attention exp-scores
__device__ float g_sentVec[Sd*Hd];
__device__ float g_hx[2][2][Hd];       // [which][parity][h]  cross-CTA h exchange
__device__ int   g_flg[2][Gn];         // [which][cta] step flags

// =====================================================================
// K0: Xp1 = inputs(2048x256) @ W_ih1^T(1024x256) + b1   (NT GEMM)
//     also zeroes the recurrence flags.
// grid: (R/64=16, T/64=32), 256 threads, 64x64 tile, K-panel 32, 4x4 micro
// =====================================================================
__global__ void __launch_bounds__(256) gemm_xp1_kernel(
    const float* __restrict__ X, const float* __restrict__ Wm,
    const float* __restrict__ bias)
{
    if (blockIdx.x == 0 && blockIdx.y == 0 && threadIdx.x < 2*Gn) {
        ((int*)g_flg)[threadIdx.x] = 0;
    }
    __shared__ float As[64][33];
    __shared__ float Bs[64][33];
    const int tid = threadIdx.x;
    const int r0 = blockIdx.x * 64;
    const int t0 = blockIdx.y * 64;
    const int tx = tid & 15;   // r micro
    const int ty = tid >> 4;   // t micro

    float acc[4][4];
#pragma unroll
    for (int i = 0; i < 4; i++)
#pragma unroll
        for (int j = 0; j < 4; j++) acc[i][j] = 0.f;

    for (int kp = 0; kp < Dd; kp += 32) {
#pragma unroll
        for (int p = 0; p < 2; p++) {
            int idx = tid + p * 256;
            int row = idx >> 3;
            int c4  = (idx & 7) * 4;
            float4 va = *(const float4*)&X [(size_t)(t0 + row) * Dd + kp + c4];
            float4 vb = *(const float4*)&Wm[(size_t)(r0 + row) * Dd + kp + c4];
            As[row][c4+0] = va.x; As[row][c4+1] = va.y; As[row][c4+2] = va.z; As[row][c4+3] = va.w;
            Bs[row][c4+0] = vb.x; Bs[row][c4+1] = vb.y; Bs[row][c4+2] = vb.z; Bs[row][c4+3] = vb.w;
        }
        __syncthreads();
#pragma unroll
        for (int k = 0; k < 32; k++) {
            float a[4], b[4];
#pragma unroll
            for (int i = 0; i < 4; i++) a[i] = As[ty*4+i][k];
#pragma unroll
            for (int j = 0; j < 4; j++) b[j] = Bs[tx*4+j][k];
#pragma unroll
            for (int i = 0; i < 4; i++)
#pragma unroll
                for (int j = 0; j < 4; j++) acc[i][j] += a[i] * b[j];
        }
        __syncthreads();
    }
    float bv[4];
#pragma unroll
    for (int j = 0; j < 4; j++) bv[j] = bias[r0 + tx*4 + j];
#pragma unroll
    for (int i = 0; i < 4; i++)
#pragma unroll
        for (int j = 0; j < 4; j++)
            g_Xp1[(size_t)(t0 + ty*4 + i) * R4H + r0 + tx*4 + j] = acc[i][j] + bv[j];
}

// =====================================================================
// K1/K5: persistent recurrent LSTM. Gn CTAs (one wave), flag-synced.
// CTA g owns hidden units [g*HSL, (g+1)*HSL) => 4*HSL = 64 gate rows.
// Weights in registers: thread (cb, r) holds W_hh[grow][cb*32 .. +32).
// h exchanged via double-buffered g_hx + release flags (monotonic).
// =====================================================================
__global__ void __launch_bounds__(RECTHREADS, 1) lstm_rec_kernel(
    const float* __restrict__ Whh, const float* __restrict__ h0,
    const float* __restrict__ c0, int nsteps, int which)
{
    const float* xp   = which ? g_Xp2  : g_Xp1;
    float*       outH = which ? g_rowH : g_Hwords;
    float*       ghb  = &g_hx[which][0][0];           // [parity*Hd + h]
    volatile int* flags = (volatile int*)g_flg[which];

    const int g   = blockIdx.x;
    const int tid = threadIdx.x;
    const int cb  = tid >> 6;        // 0..7 column block (32 cols)
    const int r   = tid & 63;        // local gate row 0..63
    const int q   = r >> 4;          // gate: 0=i 1=f 2=g 3=o
    const int rh  = r & 15;          // hidden unit within slice
    const int grow = q * Hd + g * HSL + rh;   // global gate row

    // preload weights into registers
    float wreg[32];
#pragma unroll
    for (int j = 0; j < 32; j++) wreg[j] = Whh[(size_t)grow * Hd + cb * 32 + j];

    __shared__ float hbuf[Hd];
    __shared__ float psum[8][64];
    __shared__ float gates[64];

    if (tid < Hd) hbuf[tid] = h0[tid];
    float creg = 0.f;
    if (tid < HSL) creg = c0[g * HSL + tid];
    __syncthreads();

    for (int s = 0; s < nsteps; s++) {
        // prefetch input projection for this step
        float xpv = 0.f;
        if (tid < 64) xpv = xp[(size_t)s * R4H + grow];

        // matvec partials: each thread 32 MACs, h broadcast from smem
        float hreg[32];
#pragma unroll
        for (int j = 0; j < 32; j++) hreg[j] = hbuf[cb * 32 + j];
        float acc = 0.f;
#pragma unroll
        for (int j = 0; j < 32; j++) acc += wreg[j] * hreg[j];
        psum[cb][r] = acc;
        __syncthreads();

        if (tid < 64) {
            float t = xpv;
#pragma unroll
            for (int c = 0; c < 8; c++) t += psum[c][tid];
            gates[tid] = t;
        }
        __syncthreads();

        if (tid < 32) {
            if (tid < HSL) {
                float gi = gates[tid];
                float gf = gates[16 + tid];
                float gg = gates[32 + tid];
                float go = gates[48 + tid];
                float ii = 1.f / (1.f + expf(-gi));
                float ff = 1.f / (1.f + expf(-gf));
                float oo = 1.f / (1.f + expf(-go));
                creg = ff * creg + ii * tanhf(gg);
                float hn = oo * tanhf(creg);
                int buf = (s + 1) & 1;
                ghb[buf * Hd + g * HSL + tid] = hn;             // exchange
                outH[(size_t)s * Hd + g * HSL + tid] = hn;      // history
            }
            __syncwarp(0xffffffffu);
            if (tid == 0) {
                __threadfence();
                flags[g] = s + 1;                                // release
            }
        }

        if (s + 1 < nsteps) {
            if (tid < 32) {
                const int target = s + 1;
                int v;
                do {
                    v = (tid < Gn) ? flags[tid] : target;
                } while (__any_sync(0xffffffffu, v < target));
                __threadfence();
            }
            __syncthreads();
            if (tid < Hd)
                hbuf[tid] = ((volatile float*)ghb)[(((s + 1) & 1) * Hd) + tid];
            __syncthreads();
        }
    }
}

// =====================================================================
// K2: word attention scores. One CTA per (s,w); streams 256KB of A1W.
// sc1[sw] = exp( sum_a tanh(Hw . A1W[:,a] + A1B[a]) * A1U[a] )
// =====================================================================
__global__ void __launch_bounds__(256) word_attn_kernel(
    const float* __restrict__ A1W, const float* __restrict__ A1B,
    const float* __restrict__ A1U)
{
    const int sw = blockIdx.x;
    const int tid = threadIdx.x;
    __shared__ float hw[Hd];
    __shared__ float red[256];
    hw[tid] = g_Hwords[(size_t)sw * Hd + tid];
    __syncthreads();

    const float* Wp = A1W + (size_t)sw * Hd * Hd;
    float acc = 0.f;
#pragma unroll 8
    for (int h = 0; h < Hd; h++) acc += hw[h] * __ldg(&Wp[(size_t)h * Hd + tid]);

    float u = tanhf(acc + A1B[(size_t)sw * Hd + tid]);
    float p = u * A1U[(size_t)sw * Hd + tid];
    red[tid] = p;
    __syncthreads();
    for (int off = 128; off > 0; off >>= 1) {
        if (tid < off) red[tid] += red[tid + off];
        __syncthreads();
    }
    if (tid == 0) g_sc1[sw] = expf(red[0]);
}

// =====================================================================
// K3: per-sentence softmax + sentVec + Xp2 (W_ih2 @ sentVec + b2)
// =====================================================================
__global__ void __launch_bounds__(256) sentvec_kernel(
    const float* __restrict__ W_ih2, const float* __restrict__ b2)
{
    const int s = blockIdx.x;
    const int tid = threadIdx.x;
    __shared__ float sc[Wd];
    __shared__ float svs[Hd];
    __shared__ float ssum_s;
    if (tid < Wd) sc[tid] = g_sc1[s * Wd + tid];
    __syncthreads();
    if (tid == 0) {
        float t = 0.f;
        for (int w = 0; w < Wd; w++) t += sc[w];
        ssum_s = t;
    }
    __syncthreads();
    float acc = 0.f;
    for (int w = 0; w < Wd; w++)
        acc += g_Hwords[(size_t)(s * Wd + w) * Hd + tid] * sc[w];
    float sv = acc / ssum_s;
    g_sentVec[s * Hd + tid] = sv;
    svs[tid] = sv;
    __syncthreads();
#pragma unroll
    for (int rr = 0; rr < 4; rr++) {
        int row = rr * 256 + tid;
        const float* wp = W_ih2 + (size_t)row * Hd;
        float a = b2[row];
#pragma unroll 8
        for (int d = 0; d < Hd; d++) a += __ldg(&wp[d]) * svs[d];
        g_Xp2[s * R4H + row] = a;
    }
}

// =====================================================================
// K6: sentence attention scores (uses stale last word hidden, per ref)
// =====================================================================
__global__ void __launch_bounds__(256) sent_attn_kernel(
    const float* __restrict__ A2W, const float* __restrict__ A2B,
    const float* __restrict__ A2U)
{
    const int s = blockIdx.x;
    const int tid = threadIdx.x;
    __shared__ float lastv[Hd];
    __shared__ float red[256];
    lastv[tid] = g_Hwords[(size_t)(Td - 1) * Hd + tid];
    __syncthreads();
    const float* Wp = A2W + (size_t)s * Hd * Hd;
    float acc = 0.f;
#pragma unroll 8
    for (int h = 0; h < Hd; h++) acc += lastv[h] * __ldg(&Wp[(size_t)h * Hd + tid]);
    float u = tanhf(acc + A2B[s * Hd + tid]);
    float p = u * A2U[s * Hd + tid];
    red[tid] = p;
    __syncthreads();
    for (int off = 128; off > 0; off >>= 1) {
        if (tid < off) red[tid] += red[tid + off];
        __syncthreads();
    }
    if (tid == 0) g_sc2[s] = expf(red[0]);
}

// =====================================================================
// K7: final: out = sigmoid( (rowH^T softmax(sc2)) . Wf + bf )
// =====================================================================
__global__ void __launch_bounds__(256) final_kernel(
    const float* __restrict__ Wf, const float* __restrict__ bf,
    float* __restrict__ out)
{
    const int tid = threadIdx.x;
    __shared__ float sc[Sd];
    __shared__ float red[256];
    if (tid < Sd) sc[tid] = g_sc2[tid];
    __syncthreads();
    float ssum = 0.f;
#pragma unroll
    for (int s = 0; s < Sd; s++) ssum += sc[s];
    float acc = 0.f;
#pragma unroll
    for (int s = 0; s < Sd; s++) acc += g_rowH[s * Hd + tid] * sc[s];
    float o2 = acc / ssum;
    red[tid] = o2 * Wf[tid];
    __syncthreads();
    for (int off = 128; off > 0; off >>= 1) {
        if (tid < off) red[tid] += red[tid + off];
        __syncthreads();
    }
    if (tid == 0) out[0] = 1.f / (1.f + expf(-(red[0] + bf[0])));
}

// =====================================================================
extern "C" void kernel_launch(void* const* d_in, const int* in_sizes, int n_in,
                              void* d_out, int out_size)
{
    const float* inputs = (const float*)d_in[0];
    const float* W_ih1  = (const float*)d_in[1];
    const float* W_hh1  = (const float*)d_in[2];
    const float* b1     = (const float*)d_in[3];
    const float* W_ih2  = (const float*)d_in[4];
    const float* W_hh2  = (const float*)d_in[5];
    const float* b2     = (const float*)d_in[6];
    const float* h1_0   = (const float*)d_in[7];
    const float* c1_0   = (const float*)d_in[8];
    const float* h2_0   = (const float*)d_in[9];
    const float* c2_0   = (const float*)d_in[10];
    const float* A1W    = (const float*)d_in[11];
    const float* A1B    = (const float*)d_in[12];
    const float* A1U    = (const float*)d_in[13];
    const float* A2W    = (const float*)d_in[14];
    const float* A2B    = (const float*)d_in[15];
    const float* A2U    = (const float*)d_in[16];
    const float* Wf     = (const float*)d_in[17];
    const float* bf     = (const float*)d_in[18];
    float* out = (float*)d_out;

    // K0: input projection GEMM for word LSTM (+ zero sync flags)
    dim3 g0(R4H / 64, Td / 64);
    gemm_xp1_kernel<<<g0, 256>>>(inputs, W_ih1, b1);

    // K1: word-level recurrence (2048 sequential steps, 16 CTAs)
    lstm_rec_kernel<<<Gn, RECTHREADS>>>(W_hh1, h1_0, c1_0, Td, 0);

    // K2: word attention scores (HBM-bound, 537MB of A1W)
    word_attn_kernel<<<Td, 256>>>(A1W, A1B, A1U);

    // K3: sentence vectors + sentence-LSTM input projection
    sentvec_kernel<<<Sd, 256>>>(W_ih2, b2);

    // K5: sentence-level recurrence (32 steps)
    lstm_rec_kernel<<<Gn, RECTHREADS>>>(W_hh2, h2_0, c2_0, Sd, 1);

    // K6: sentence attention scores
    sent_attn_kernel<<<Sd, 256>>>(A2W, A2B, A2U);

    // K7: final output
    final_kernel<<<1, 256>>>(Wf, bf, out);
}

// round 2
// speedup vs baseline: 2.1255x; 2.1255x over previous
#include <cuda_runtime.h>
#include <math.h>

// Problem dims
#define Sd 32
#define Wd 64
#define Dd 256
#define Hd 256
#define Td (Sd*Wd)      // 2048
#define R4H 1024        // 4*H
#define Gn 16           // CTAs in recurrence
#define HSL (Hd/Gn)     // 16 hidden units per CTA
#define RECTHREADS 512

// ---------------- device scratch (static, no allocation) ----------------
__device__ float g_Xp1[Td*R4H];        // 8 MB: W_ih1@x + b1 for all word steps
__device__ float g_Xp2[Sd*R4H];        // W_ih2@sentVec + b2
__device__ float g_Hwords[Td*Hd];      // all word-LSTM hiddens
__device__ float g_rowH[Sd*Hd];        // all sentence-LSTM hiddens
__device__ float g_sc1[Td];            // word attention exp-scores
__device__ float g_sc2[Sd];            // sentence attention exp-scores
__device__ float g_sentVec[Sd*Hd];
// tagged h exchange: [which][parity][h] = {tag(hi32), h_bits(lo32)}
__device__ unsigned long long g_hx2[2][2][Hd];

// fast, saturating activations (__expf max err ~2ulp; safe for 1e-3 budget)
__device__ __forceinline__ float fsig(float x) {
    return __fdividef(1.f, 1.f + __expf(-x));
}
__device__ __forceinline__ float ftanh(float x) {
    // 1 - 2/(e^{2x}+1): e->inf => 1, e->0 => -1 (no NaN at extremes)
    return 1.f - __fdividef(2.f, __expf(2.f * x) + 1.f);
}

// =====================================================================
// K0: Xp1 = inputs(2048x256) @ W_ih1^T(1024x256) + b1   (NT GEMM)
//     block(0,0) also zeroes the exchange tag buffers (replay safety).
// =====================================================================
__global__ void __launch_bounds__(256) gemm_xp1_kernel(
    const float* __restrict__ X, const float* __restrict__ Wm,
    const float* __restrict__ bias)
{
    if (blockIdx.x == 0 && blockIdx.y == 0) {
        unsigned long long* t = &g_hx2[0][0][0];
#pragma unroll
        for (int p = 0; p < 4; p++) t[threadIdx.x + p * 256] = 0ull;
    }
    __shared__ float As[64][33];
    __shared__ float Bs[64][33];
    const int tid = threadIdx.x;
    const int r0 = blockIdx.x * 64;
    const int t0 = blockIdx.y * 64;
    const int tx = tid & 15;   // r micro
    const int ty = tid >> 4;   // t micro

    float acc[4][4];
#pragma unroll
    for (int i = 0; i < 4; i++)
#pragma unroll
        for (int j = 0; j < 4; j++) acc[i][j] = 0.f;

    for (int kp = 0; kp < Dd; kp += 32) {
#pragma unroll
        for (int p = 0; p < 2; p++) {
            int idx = tid + p * 256;
            int row = idx >> 3;
            int c4  = (idx & 7) * 4;
            float4 va = *(const float4*)&X [(size_t)(t0 + row) * Dd + kp + c4];
            float4 vb = *(const float4*)&Wm[(size_t)(r0 + row) * Dd + kp + c4];
            As[row][c4+0] = va.x; As[row][c4+1] = va.y; As[row][c4+2] = va.z; As[row][c4+3] = va.w;
            Bs[row][c4+0] = vb.x; Bs[row][c4+1] = vb.y; Bs[row][c4+2] = vb.z; Bs[row][c4+3] = vb.w;
        }
        __syncthreads();
#pragma unroll
        for (int k = 0; k < 32; k++) {
            float a[4], b[4];
#pragma unroll
            for (int i = 0; i < 4; i++) a[i] = As[ty*4+i][k];
#pragma unroll
            for (int j = 0; j < 4; j++) b[j] = Bs[tx*4+j][k];
#pragma unroll
            for (int i = 0; i < 4; i++)
#pragma unroll
                for (int j = 0; j < 4; j++) acc[i][j] += a[i] * b[j];
        }
        __syncthreads();
    }
    float bv[4];
#pragma unroll
    for (int j = 0; j < 4; j++) bv[j] = bias[r0 + tx*4 + j];
#pragma unroll
    for (int i = 0; i < 4; i++)
#pragma unroll
        for (int j = 0; j < 4; j++)
            g_Xp1[(size_t)(t0 + ty*4 + i) * R4H + r0 + tx*4 + j] = acc[i][j] + bv[j];
}

// =====================================================================
// K1/K5: persistent recurrent LSTM. Gn CTAs (one wave).
// Per-step exchange: 64-bit tagged stores {step, h}; readers poll their
// own element directly (single L2 round trip, no fences, no flags).
// Column-reduce + gate math confined to warp 0 (LDS + 2x SHFL.XOR).
// =====================================================================
__global__ void __launch_bounds__(RECTHREADS, 1) lstm_rec_kernel(
    const float* __restrict__ Whh, const float* __restrict__ h0,
    const float* __restrict__ c0, int nsteps, int which)
{
    const float* xp   = which ? g_Xp2  : g_Xp1;
    float*       outH = which ? g_rowH : g_Hwords;
    unsigned long long* exbuf = &g_hx2[which][0][0];   // [parity*Hd + h]

    const int g   = blockIdx.x;
    const int tid = threadIdx.x;
    const int cb  = tid >> 6;        // 0..7 column block (32 cols)
    const int r   = tid & 63;        // local gate row 0..63
    const int grow = (r >> 4) * Hd + g * HSL + (r & 15);   // global gate row

    // rows warp0 will reduce: ra = lane, rb = lane+32
    const int lane = tid & 31;
    const int growA = (lane >> 4) * Hd + g * HSL + (lane & 15);          // q=0/1
    const int growB = ((lane + 32) >> 4) * Hd + g * HSL + (lane & 15);   // q=2/3

    // preload weights into registers
    float wreg[32];
#pragma unroll
    for (int j = 0; j < 32; j++) wreg[j] = Whh[(size_t)grow * Hd + cb * 32 + j];

    __shared__ float hbuf[Hd];
    __shared__ float psum[8][64];

    if (tid < Hd) hbuf[tid] = h0[tid];
    float creg = 0.f;
    if (tid < HSL) creg = c0[g * HSL + tid];
    __syncthreads();

    for (int s = 0; s < nsteps; s++) {
        // prefetch input projection for this step (warp 0 only uses it)
        float xpa = 0.f, xpb = 0.f;
        if (tid < 32) {
            xpa = __ldg(&xp[(size_t)s * R4H + growA]);
            xpb = __ldg(&xp[(size_t)s * R4H + growB]);
        }

        // matvec partials: 32 MACs/thread, h broadcast from smem
        float acc = 0.f;
#pragma unroll
        for (int j = 0; j < 32; j++) acc += wreg[j] * hbuf[cb * 32 + j];
        psum[cb][r] = acc;
        __syncthreads();

        if (tid < 32) {
            // reduce 8 column-blocks for rows lane and lane+32
            float t1 = xpa, t2 = xpb;
#pragma unroll
            for (int c = 0; c < 8; c++) {
                t1 += psum[c][lane];
                t2 += psum[c][lane + 32];
            }
            // lanes 0..15: t1=i, t2=g ; lanes 16..31: t1=f, t2=o
            float fo1 = __shfl_xor_sync(0xffffffffu, t1, 16);
            float fo2 = __shfl_xor_sync(0xffffffffu, t2, 16);
            if (lane < 16) {
                float ii = fsig(t1);
                float ff = fsig(fo1);
                float oo = fsig(fo2);
                creg = ff * creg + ii * ftanh(t2);
                float hn = oo * ftanh(creg);
                int hidx = g * HSL + lane;
                outH[(size_t)s * Hd + hidx] = hn;
                // tagged atomic 64-bit release: {tag=s+1, value}
                unsigned long long packed =
                    ((unsigned long long)(unsigned)(s + 1) << 32) |
                    (unsigned long long)__float_as_uint(hn);
                *((volatile unsigned long long*)&exbuf[(((s + 1) & 1) * Hd) + hidx]) = packed;
            }
        }

        if (s + 1 < nsteps) {
            const unsigned target = (unsigned)(s + 1);
            if (tid < Hd) {
                volatile unsigned long long* p =
                    &exbuf[(((s + 1) & 1) * Hd) + tid];
                unsigned long long v;
                do { v = *p; } while ((unsigned)(v >> 32) != target);
                hbuf[tid] = __uint_as_float((unsigned)(v & 0xffffffffu));
            }
            __syncthreads();
        }
    }
}

// =====================================================================
// K2: word attention scores. One CTA per (s,w); streams 256KB of A1W.
// =====================================================================
__global__ void __launch_bounds__(256) word_attn_kernel(
    const float* __restrict__ A1W, const float* __restrict__ A1B,
    const float* __restrict__ A1U)
{
    const int sw = blockIdx.x;
    const int tid = threadIdx.x;
    __shared__ float hw[Hd];
    __shared__ float red[256];
    hw[tid] = g_Hwords[(size_t)sw * Hd + tid];
    __syncthreads();

    const float* Wp = A1W + (size_t)sw * Hd * Hd;
    float acc = 0.f;
#pragma unroll 8
    for (int h = 0; h < Hd; h++) acc += hw[h] * __ldg(&Wp[(size_t)h * Hd + tid]);

    float u = tanhf(acc + A1B[(size_t)sw * Hd + tid]);
    float p = u * A1U[(size_t)sw * Hd + tid];
    red[tid] = p;
    __syncthreads();
    for (int off = 128; off > 0; off >>= 1) {
        if (tid < off) red[tid] += red[tid + off];
        __syncthreads();
    }
    if (tid == 0) g_sc1[sw] = expf(red[0]);
}

// =====================================================================
// K3: per-sentence softmax + sentVec (coalesced over h)
// =====================================================================
__global__ void __launch_bounds__(256) sentvec_kernel()
{
    const int s = blockIdx.x;
    const int tid = threadIdx.x;
    __shared__ float sc[Wd];
    __shared__ float ssum_s;
    if (tid < Wd) sc[tid] = g_sc1[s * Wd + tid];
    __syncthreads();
    if (tid == 0) {
        float t = 0.f;
        for (int w = 0; w < Wd; w++) t += sc[w];
        ssum_s = t;
    }
    __syncthreads();
    float acc = 0.f;
#pragma unroll 8
    for (int w = 0; w < Wd; w++)
        acc += g_Hwords[(size_t)(s * Wd + w) * Hd + tid] * sc[w];
    g_sentVec[s * Hd + tid] = acc / ssum_s;
}

// =====================================================================
// K4: Xp2 = W_ih2 @ sentVec + b2, warp-per-row coalesced
// grid (Sd, 4), 256 threads: block (s,rb) does rows rb*256..+255
// =====================================================================
__global__ void __launch_bounds__(256) xp2_kernel(
    const float* __restrict__ W_ih2, const float* __restrict__ b2)
{
    const int s  = blockIdx.x;
    const int rb = blockIdx.y;
    const int tid = threadIdx.x;
    const int w   = tid >> 5;
    const int lane = tid & 31;
    __shared__ float svs[Hd];
    if (tid < Hd) svs[tid] = g_sentVec[s * Hd + tid];
    __syncthreads();

#pragma unroll
    for (int i = 0; i < 32; i++) {
        int row = rb * 256 + w * 32 + i;
        const float* wp = W_ih2 + (size_t)row * Hd;
        float a = 0.f;
#pragma unroll
        for (int d = 0; d < 8; d++)
            a += __ldg(&wp[lane + d * 32]) * svs[lane + d * 32];
#pragma unroll
        for (int off = 16; off > 0; off >>= 1)
            a += __shfl_xor_sync(0xffffffffu, a, off);
        if (lane == 0) g_Xp2[s * R4H + row] = a + b2[row];
    }
}

// =====================================================================
// K6: sentence attention scores (stale last word hidden, per reference)
// =====================================================================
__global__ void __launch_bounds__(256) sent_attn_kernel(
    const float* __restrict__ A2W, const float* __restrict__ A2B,
    const float* __restrict__ A2U)
{
    const int s = blockIdx.x;
    const int tid = threadIdx.x;
    __shared__ float lastv[Hd];
    __shared__ float red[256];
    lastv[tid] = g_Hwords[(size_t)(Td - 1) * Hd + tid];
    __syncthreads();
    const float* Wp = A2W + (size_t)s * Hd * Hd;
    float acc = 0.f;
#pragma unroll 8
    for (int h = 0; h < Hd; h++) acc += lastv[h] * __ldg(&Wp[(size_t)h * Hd + tid]);
    float u = tanhf(acc + A2B[s * Hd + tid]);
    float p = u * A2U[s * Hd + tid];
    red[tid] = p;
    __syncthreads();
    for (int off = 128; off > 0; off >>= 1) {
        if (tid < off) red[tid] += red[tid + off];
        __syncthreads();
    }
    if (tid == 0) g_sc2[s] = expf(red[0]);
}

// =====================================================================
// K7: final: out = sigmoid( (rowH^T softmax(sc2)) . Wf + bf )
// =====================================================================
__global__ void __launch_bounds__(256) final_kernel(
    const float* __restrict__ Wf, const float* __restrict__ bf,
    float* __restrict__ out)
{
    const int tid = threadIdx.x;
    __shared__ float sc[Sd];
    __shared__ float red[256];
    if (tid < Sd) sc[tid] = g_sc2[tid];
    __syncthreads();
    float ssum = 0.f;
#pragma unroll
    for (int s = 0; s < Sd; s++) ssum += sc[s];
    float acc = 0.f;
#pragma unroll
    for (int s = 0; s < Sd; s++) acc += g_rowH[s * Hd + tid] * sc[s];
    float o2 = acc / ssum;
    red[tid] = o2 * Wf[tid];
    __syncthreads();
    for (int off = 128; off > 0; off >>= 1) {
        if (tid < off) red[tid] += red[tid + off];
        __syncthreads();
    }
    if (tid == 0) out[0] = 1.f / (1.f + expf(-(red[0] + bf[0])));
}

// =====================================================================
extern "C" void kernel_launch(void* const* d_in, const int* in_sizes, int n_in,
                              void* d_out, int out_size)
{
    const float* inputs = (const float*)d_in[0];
    const float* W_ih1  = (const float*)d_in[1];
    const float* W_hh1  = (const float*)d_in[2];
    const float* b1     = (const float*)d_in[3];
    const float* W_ih2  = (const float*)d_in[4];
    const float* W_hh2  = (const float*)d_in[5];
    const float* b2     = (const float*)d_in[6];
    const float* h1_0   = (const float*)d_in[7];
    const float* c1_0   = (const float*)d_in[8];
    const float* h2_0   = (const float*)d_in[9];
    const float* c2_0   = (const float*)d_in[10];
    const float* A1W    = (const float*)d_in[11];
    const float* A1B    = (const float*)d_in[12];
    const float* A1U    = (const float*)d_in[13];
    const float* A2W    = (const float*)d_in[14];
    const float* A2B    = (const float*)d_in[15];
    const float* A2U    = (const float*)d_in[16];
    const float* Wf     = (const float*)d_in[17];
    const float* bf     = (const float*)d_in[18];
    float* out = (float*)d_out;

    // K0: input projection GEMM for word LSTM (+ zero exchange tags)
    dim3 g0(R4H / 64, Td / 64);
    gemm_xp1_kernel<<<g0, 256>>>(inputs, W_ih1, b1);

    // K1: word-level recurrence (2048 sequential steps, 16 CTAs)
    lstm_rec_kernel<<<Gn, RECTHREADS>>>(W_hh1, h1_0, c1_0, Td, 0);

    // K2: word attention scores (HBM-bound, 537MB of A1W)
    word_attn_kernel<<<Td, 256>>>(A1W, A1B, A1U);

    // K3: sentence vectors
    sentvec_kernel<<<Sd, 256>>>();

    // K4: sentence-LSTM input projection (warp-per-row, coalesced)
    dim3 g4(Sd, 4);
    xp2_kernel<<<g4, 256>>>(W_ih2, b2);

    // K5: sentence-level recurrence (32 steps)
    lstm_rec_kernel<<<Gn, RECTHREADS>>>(W_hh2, h2_0, c2_0, Sd, 1);

    // K6: sentence attention scores
    sent_attn_kernel<<<Sd, 256>>>(A2W, A2B, A2U);

    // K7: final output
    final_kernel<<<1, 256>>>(Wf, bf, out);
}

// round 3
// speedup vs baseline: 3.1073x; 1.4619x over previous
#include <cuda_runtime.h>
#include <math.h>

// Problem dims
#define Sd 32
#define Wd 64
#define Dd 256
#define Hd 256
#define Td (Sd*Wd)      // 2048
#define R4H 1024        // 4*H
#define Gn 16           // CTAs in recurrence (one 16-CTA cluster)
#define HSL (Hd/Gn)     // 16 hidden units per CTA
#define RECTHREADS 512

// ---------------- device scratch (static, no allocation) ----------------
__device__ float g_Xp1[Td*R4H];        // 8 MB: W_ih1@x + b1 for all word steps
__device__ float g_Xp2[Sd*R4H];        // W_ih2@sentVec + b2
__device__ float g_Hwords[Td*Hd];      // all word-LSTM hiddens
__device__ float g_rowH[Sd*Hd];        // all sentence-LSTM hiddens
__device__ float g_sc1[Td];            // word attention exp-scores
__device__ float g_sc2[Sd];            // sentence attention exp-scores
__device__ float g_sentVec[Sd*Hd];

// fast, saturating activations
__device__ __forceinline__ float fsig(float x) {
    return __fdividef(1.f, 1.f + __expf(-x));
}
__device__ __forceinline__ float ftanh(float x) {
    return 1.f - __fdividef(2.f, __expf(2.f * x) + 1.f);
}

// packed f32x2 helpers
__device__ __forceinline__ unsigned long long fma2(
    unsigned long long a, unsigned long long b, unsigned long long c) {
    unsigned long long d;
    asm("fma.rn.f32x2 %0, %1, %2, %3;" : "=l"(d) : "l"(a), "l"(b), "l"(c));
    return d;
}
__device__ __forceinline__ unsigned long long add2(
    unsigned long long a, unsigned long long b) {
    unsigned long long d;
    asm("add.rn.f32x2 %0, %1, %2;" : "=l"(d) : "l"(a), "l"(b));
    return d;
}

// cluster / mbarrier helpers
__device__ __forceinline__ unsigned smem_u32(const void* p) {
    return (unsigned)__cvta_generic_to_shared(p);
}
__device__ __forceinline__ unsigned mapa_u32(unsigned addr, unsigned rank) {
    unsigned r;
    asm("mapa.shared::cluster.u32 %0, %1, %2;" : "=r"(r) : "r"(addr), "r"(rank));
    return r;
}
__device__ __forceinline__ void st_async_b32(unsigned raddr, float v, unsigned rmbar) {
    asm volatile(
        "st.async.shared::cluster.mbarrier::complete_tx::bytes.b32 [%0], %1, [%2];"
        :: "r"(raddr), "r"(__float_as_uint(v)), "r"(rmbar) : "memory");
}
__device__ __forceinline__ void mbar_init(unsigned mbar, unsigned cnt) {
    asm volatile("mbarrier.init.shared.b64 [%0], %1;" :: "r"(mbar), "r"(cnt) : "memory");
}
__device__ __forceinline__ void mbar_expect_tx(unsigned mbar, unsigned bytes) {
    asm volatile("mbarrier.arrive.expect_tx.shared.b64 _, [%0], %1;"
                 :: "r"(mbar), "r"(bytes) : "memory");
}
__device__ __forceinline__ void mbar_wait_parity(unsigned mbar, unsigned parity) {
    asm volatile(
        "{\n\t"
        ".reg .pred P1;\n\t"
        "WAIT_%=:\n\t"
        "mbarrier.try_wait.parity.acquire.cluster.shared::cta.b64 P1, [%0], %1, 0x989680;\n\t"
        "@P1 bra DONE_%=;\n\t"
        "bra WAIT_%=;\n\t"
        "DONE_%=:\n\t"
        "}"
        :: "r"(mbar), "r"(parity) : "memory");
}

// =====================================================================
// K0: Xp1 = inputs(2048x256) @ W_ih1^T(1024x256) + b1   (NT GEMM)
// 128(t) x 64(r) tiles, 256 threads, 8x4 micro, K-panel 32
// grid: (R4H/64=16, Td/128=16)
// =====================================================================
__global__ void __launch_bounds__(256) gemm_xp1_kernel(
    const float* __restrict__ X, const float* __restrict__ Wm,
    const float* __restrict__ bias)
{
    __shared__ float As[128][33];
    __shared__ float Bs[64][33];
    const int tid = threadIdx.x;
    const int r0 = blockIdx.x * 64;
    const int t0 = blockIdx.y * 128;
    const int tx = tid & 15;   // r micro (4 cols)
    const int ty = tid >> 4;   // t micro (8 rows)

    float acc[8][4];
#pragma unroll
    for (int i = 0; i < 8; i++)
#pragma unroll
        for (int j = 0; j < 4; j++) acc[i][j] = 0.f;

    for (int kp = 0; kp < Dd; kp += 32) {
#pragma unroll
        for (int p = 0; p < 4; p++) {
            int idx = tid + p * 256;
            int row = idx >> 3;
            int c4  = (idx & 7) * 4;
            float4 va = *(const float4*)&X[(size_t)(t0 + row) * Dd + kp + c4];
            As[row][c4+0] = va.x; As[row][c4+1] = va.y;
            As[row][c4+2] = va.z; As[row][c4+3] = va.w;
        }
#pragma unroll
        for (int p = 0; p < 2; p++) {
            int idx = tid + p * 256;
            int row = idx >> 3;
            int c4  = (idx & 7) * 4;
            float4 vb = *(const float4*)&Wm[(size_t)(r0 + row) * Dd + kp + c4];
            Bs[row][c4+0] = vb.x; Bs[row][c4+1] = vb.y;
            Bs[row][c4+2] = vb.z; Bs[row][c4+3] = vb.w;
        }
        __syncthreads();
#pragma unroll
        for (int k = 0; k < 32; k++) {
            float a[8], b[4];
#pragma unroll
            for (int i = 0; i < 8; i++) a[i] = As[ty*8+i][k];
#pragma unroll
            for (int j = 0; j < 4; j++) b[j] = Bs[tx*4+j][k];
#pragma unroll
            for (int i = 0; i < 8; i++)
#pragma unroll
                for (int j = 0; j < 4; j++) acc[i][j] += a[i] * b[j];
        }
        __syncthreads();
    }
    float4 bv = *(const float4*)&bias[r0 + tx*4];
#pragma unroll
    for (int i = 0; i < 8; i++) {
        float4 o;
        o.x = acc[i][0] + bv.x; o.y = acc[i][1] + bv.y;
        o.z = acc[i][2] + bv.z; o.w = acc[i][3] + bv.w;
        *(float4*)&g_Xp1[(size_t)(t0 + ty*8 + i) * R4H + r0 + tx*4] = o;
    }
}

// =====================================================================
// K1/K5: persistent recurrent LSTM. 16-CTA cluster, DSMEM push exchange.
// CTA g owns hidden [g*16, g*16+16) => 64 gate rows; W_hh in registers
// as f32x2 pairs. Per step each CTA pushes its 16 new h values into every
// peer's hbuf via st.async; receivers wait one mbarrier phase.
// Two alternating mbarriers (one per buffer parity) bound producer skew.
// =====================================================================
__global__ void __launch_bounds__(RECTHREADS, 1) lstm_rec_kernel(
    const float* __restrict__ Whh, const float* __restrict__ h0,
    const float* __restrict__ c0, int nsteps, int which)
{
    const float* xp   = which ? g_Xp2  : g_Xp1;
    float*       outH = which ? g_rowH : g_Hwords;

    const int g    = blockIdx.x;          // == cluster rank (grid == cluster)
    const int tid  = threadIdx.x;
    const int cb   = tid >> 6;            // 0..7 column block (32 cols)
    const int r    = tid & 63;            // local gate row 0..63
    const int lane = tid & 31;
    const int grow  = (r >> 4) * Hd + g * HSL + (r & 15);
    const int growA = (lane >> 4) * Hd + g * HSL + (lane & 15);         // q=0/1
    const int growB = ((lane + 32) >> 4) * Hd + g * HSL + (lane & 15);  // q=2/3

    // preload weights as packed f32x2 (columns cb*32 .. +32)
    unsigned long long wreg[16];
#pragma unroll
    for (int j = 0; j < 16; j++)
        wreg[j] = *(const unsigned long long*)(Whh + (size_t)grow * Hd + cb * 32 + 2 * j);

    __shared__ __align__(16) float hbuf[2][Hd];
    __shared__ float psum[8][64];
    __shared__ __align__(8) unsigned long long s_mbar[2];

    if (tid < Hd) hbuf[0][tid] = h0[tid];
    float creg = 0.f;
    if (tid < HSL) creg = c0[g * HSL + tid];
    if (tid == 0) {
        mbar_init(smem_u32(&s_mbar[0]), 1);
        mbar_init(smem_u32(&s_mbar[1]), 1);
    }
    __syncthreads();
    // all mbarriers visible cluster-wide before any st.async
    asm volatile("barrier.cluster.arrive.aligned;" ::: "memory");
    asm volatile("barrier.cluster.wait.aligned;"   ::: "memory");

    const unsigned hb_u = smem_u32(&hbuf[0][0]);
    const unsigned mb_u = smem_u32(&s_mbar[0]);

    // each warp0 lane pushes to 8 peers: lanes 0-15 -> peers 0-7, 16-31 -> 8-15
    unsigned rh[8], rm[8];
    if (tid < 32) {
#pragma unroll
        for (int p = 0; p < 8; p++) {
            unsigned peer = (unsigned)((lane >> 4) * 8 + p);
            rh[p] = mapa_u32(hb_u, peer);
            rm[p] = mapa_u32(mb_u, peer);
        }
    }

    for (int s = 0; s < nsteps; s++) {
        // prefetch input projection for this step (consumed by warp0 reduce)
        float xpa = 0.f, xpb = 0.f;
        if (tid < 32) {
            xpa = __ldg(&xp[(size_t)s * R4H + growA]);
            xpb = __ldg(&xp[(size_t)s * R4H + growB]);
        }

        // matvec partials: 16 packed FMAs per thread
        const unsigned long long* hp =
            (const unsigned long long*)&hbuf[s & 1][cb * 32];
        unsigned long long a0 = 0ull, a1 = 0ull, a2 = 0ull, a3 = 0ull;
#pragma unroll
        for (int j = 0; j < 16; j += 4) {
            a0 = fma2(wreg[j+0], hp[j+0], a0);
            a1 = fma2(wreg[j+1], hp[j+1], a1);
            a2 = fma2(wreg[j+2], hp[j+2], a2);
            a3 = fma2(wreg[j+3], hp[j+3], a3);
        }
        unsigned long long at = add2(add2(a0, a1), add2(a2, a3));
        unsigned lo32, hi32;
        asm("mov.b64 {%0, %1}, %2;" : "=r"(lo32), "=r"(hi32) : "l"(at));
        psum[cb][r] = __uint_as_float(lo32) + __uint_as_float(hi32);
        __syncthreads();

        if (tid < 32) {
            float t1 = xpa, t2 = xpb;
#pragma unroll
            for (int c = 0; c < 8; c++) {
                t1 += psum[c][lane];
                t2 += psum[c][lane + 32];
            }
            // lanes 0..15: t1=i, t2=g ; lanes 16..31: t1=f, t2=o
            float fo1 = __shfl_xor_sync(0xffffffffu, t1, 16);
            float fo2 = __shfl_xor_sync(0xffffffffu, t2, 16);
            float hn = 0.f;
            if (lane < 16) {
                float ii = fsig(t1);
                float ff = fsig(fo1);
                float oo = fsig(fo2);
                creg = ff * creg + ii * ftanh(t2);
                hn = oo * ftanh(creg);
            }
            float hnb = __shfl_sync(0xffffffffu, hn, lane & 15);
            if (s + 1 < nsteps) {
                const int nb = (s + 1) & 1;
                if (lane == 0) mbar_expect_tx(mb_u + nb * 8, Hd * 4);
                unsigned off = (unsigned)((nb * Hd + g * HSL + (lane & 15)) * 4);
#pragma unroll
                for (int p = 0; p < 8; p++)
                    st_async_b32(rh[p] + off, hnb, rm[p] + nb * 8);
            }
            if (lane < 16)
                outH[(size_t)s * Hd + g * HSL + lane] = hn;
        }

        if (s + 1 < nsteps) {
            mbar_wait_parity(mb_u + ((s + 1) & 1) * 8, (unsigned)((s >> 1) & 1));
        }
    }

    asm volatile("barrier.cluster.arrive.aligned;" ::: "memory");
    asm volatile("barrier.cluster.wait.aligned;"   ::: "memory");
}

// =====================================================================
// K2: word attention scores. One CTA per (s,w); streams 256KB of A1W.
// =====================================================================
__global__ void __launch_bounds__(256) word_attn_kernel(
    const float* __restrict__ A1W, const float* __restrict__ A1B,
    const float* __restrict__ A1U)
{
    const int sw = blockIdx.x;
    const int tid = threadIdx.x;
    __shared__ float hw[Hd];
    __shared__ float red[256];
    hw[tid] = g_Hwords[(size_t)sw * Hd + tid];
    __syncthreads();

    const float* Wp = A1W + (size_t)sw * Hd * Hd;
    float acc = 0.f;
#pragma unroll 8
    for (int h = 0; h < Hd; h++) acc += hw[h] * __ldg(&Wp[(size_t)h * Hd + tid]);

    float u = tanhf(acc + A1B[(size_t)sw * Hd + tid]);
    float p = u * A1U[(size_t)sw * Hd + tid];
    red[tid] = p;
    __syncthreads();
    for (int off = 128; off > 0; off >>= 1) {
        if (tid < off) red[tid] += red[tid + off];
        __syncthreads();
    }
    if (tid == 0) g_sc1[sw] = expf(red[0]);
}

// =====================================================================
// K3: per-sentence softmax + sentVec (coalesced over h)
// =====================================================================
__global__ void __launch_bounds__(256) sentvec_kernel()
{
    const int s = blockIdx.x;
    const int tid = threadIdx.x;
    __shared__ float sc[Wd];
    __shared__ float ssum_s;
    if (tid < Wd) sc[tid] = g_sc1[s * Wd + tid];
    __syncthreads();
    if (tid == 0) {
        float t = 0.f;
        for (int w = 0; w < Wd; w++) t += sc[w];
        ssum_s = t;
    }
    __syncthreads();
    float acc = 0.f;
#pragma unroll 8
    for (int w = 0; w < Wd; w++)
        acc += g_Hwords[(size_t)(s * Wd + w) * Hd + tid] * sc[w];
    g_sentVec[s * Hd + tid] = acc / ssum_s;
}

// =====================================================================
// K4: Xp2 = W_ih2 @ sentVec + b2, warp-per-row coalesced
// =====================================================================
__global__ void __launch_bounds__(256) xp2_kernel(
    const float* __restrict__ W_ih2, const float* __restrict__ b2)
{
    const int s  = blockIdx.x;
    const int rb = blockIdx.y;
    const int tid = threadIdx.x;
    const int w   = tid >> 5;
    const int lane = tid & 31;
    __shared__ float svs[Hd];
    if (tid < Hd) svs[tid] = g_sentVec[s * Hd + tid];
    __syncthreads();

#pragma unroll
    for (int i = 0; i < 32; i++) {
        int row = rb * 256 + w * 32 + i;
        const float* wp = W_ih2 + (size_t)row * Hd;
        float a = 0.f;
#pragma unroll
        for (int d = 0; d < 8; d++)
            a += __ldg(&wp[lane + d * 32]) * svs[lane + d * 32];
#pragma unroll
        for (int off = 16; off > 0; off >>= 1)
            a += __shfl_xor_sync(0xffffffffu, a, off);
        if (lane == 0) g_Xp2[s * R4H + row] = a + b2[row];
    }
}

// =====================================================================
// K6: sentence attention scores (stale last word hidden, per reference)
// =====================================================================
__global__ void __launch_bounds__(256) sent_attn_kernel(
    const float* __restrict__ A2W, const float* __restrict__ A2B,
    const float* __restrict__ A2U)
{
    const int s = blockIdx.x;
    const int tid = threadIdx.x;
    __shared__ float lastv[Hd];
    __shared__ float red[256];
    lastv[tid] = g_Hwords[(size_t)(Td - 1) * Hd + tid];
    __syncthreads();
    const float* Wp = A2W + (size_t)s * Hd * Hd;
    float acc = 0.f;
#pragma unroll 8
    for (int h = 0; h < Hd; h++) acc += lastv[h] * __ldg(&Wp[(size_t)h * Hd + tid]);
    float u = tanhf(acc + A2B[s * Hd + tid]);
    float p = u * A2U[s * Hd + tid];
    red[tid] = p;
    __syncthreads();
    for (int off = 128; off > 0; off >>= 1) {
        if (tid < off) red[tid] += red[tid + off];
        __syncthreads();
    }
    if (tid == 0) g_sc2[s] = expf(red[0]);
}

// =====================================================================
// K7: final: out = sigmoid( (rowH^T softmax(sc2)) . Wf + bf )
// =====================================================================
__global__ void __launch_bounds__(256) final_kernel(
    const float* __restrict__ Wf, const float* __restrict__ bf,
    float* __restrict__ out)
{
    const int tid = threadIdx.x;
    __shared__ float sc[Sd];
    __shared__ float red[256];
    if (tid < Sd) sc[tid] = g_sc2[tid];
    __syncthreads();
    float ssum = 0.f;
#pragma unroll
    for (int s = 0; s < Sd; s++) ssum += sc[s];
    float acc = 0.f;
#pragma unroll
    for (int s = 0; s < Sd; s++) acc += g_rowH[s * Hd + tid] * sc[s];
    float o2 = acc / ssum;
    red[tid] = o2 * Wf[tid];
    __syncthreads();
    for (int off = 128; off > 0; off >>= 1) {
        if (tid < off) red[tid] += red[tid + off];
        __syncthreads();
    }
    if (tid == 0) out[0] = 1.f / (1.f + expf(-(red[0] + bf[0])));
}

// =====================================================================
extern "C" void kernel_launch(void* const* d_in, const int* in_sizes, int n_in,
                              void* d_out, int out_size)
{
    const float* inputs = (const float*)d_in[0];
    const float* W_ih1  = (const float*)d_in[1];
    const float* W_hh1  = (const float*)d_in[2];
    const float* b1     = (const float*)d_in[3];
    const float* W_ih2  = (const float*)d_in[4];
    const float* W_hh2  = (const float*)d_in[5];
    const float* b2     = (const float*)d_in[6];
    const float* h1_0   = (const float*)d_in[7];
    const float* c1_0   = (const float*)d_in[8];
    const float* h2_0   = (const float*)d_in[9];
    const float* c2_0   = (const float*)d_in[10];
    const float* A1W    = (const float*)d_in[11];
    const float* A1B    = (const float*)d_in[12];
    const float* A1U    = (const float*)d_in[13];
    const float* A2W    = (const float*)d_in[14];
    const float* A2B    = (const float*)d_in[15];
    const float* A2U    = (const float*)d_in[16];
    const float* Wf     = (const float*)d_in[17];
    const float* bf     = (const float*)d_in[18];
    float* out = (float*)d_out;

    // allow 16-CTA (non-portable) cluster for the recurrence kernel
    cudaFuncSetAttribute((const void*)lstm_rec_kernel,
                         cudaFuncAttributeNonPortableClusterSizeAllowed, 1);

    // K0: input projection GEMM for word LSTM
    dim3 g0(R4H / 64, Td / 128);
    gemm_xp1_kernel<<<g0, 256>>>(inputs, W_ih1, b1);

    // cluster launch config for the recurrence
    cudaLaunchConfig_t cfg = {};
    cfg.gridDim  = dim3(Gn, 1, 1);
    cfg.blockDim = dim3(RECTHREADS, 1, 1);
    cfg.dynamicSmemBytes = 0;
    cfg.stream = 0;
    cudaLaunchAttribute attrs[1];
    attrs[0].id = cudaLaunchAttributeClusterDimension;
    attrs[0].val.clusterDim.x = Gn;
    attrs[0].val.clusterDim.y = 1;
    attrs[0].val.clusterDim.z = 1;
    cfg.attrs = attrs;
    cfg.numAttrs = 1;

    // K1: word-level recurrence (2048 sequential steps, 16-CTA cluster)
    cudaLaunchKernelEx(&cfg, lstm_rec_kernel, W_hh1, h1_0, c1_0, (int)Td, 0);

    // K2: word attention scores (HBM-bound, 537MB of A1W)
    word_attn_kernel<<<Td, 256>>>(A1W, A1B, A1U);

    // K3: sentence vectors
    sentvec_kernel<<<Sd, 256>>>();

    // K4: sentence-LSTM input projection
    dim3 g4(Sd, 4);
    xp2_kernel<<<g4, 256>>>(W_ih2, b2);

    // K5: sentence-level recurrence (32 steps)
    cudaLaunchKernelEx(&cfg, lstm_rec_kernel, W_hh2, h2_0, c2_0, (int)Sd, 1);

    // K6: sentence attention scores
    sent_attn_kernel<<<Sd, 256>>>(A2W, A2B, A2U);

    // K7: final output
    final_kernel<<<1, 256>>>(Wf, bf, out);
}